// round 6
// baseline (speedup 1.0000x reference)
#include <cuda_runtime.h>
#include <math_constants.h>

#define NF    1024
#define NK    (NF + 1)
#define ND    256               // output units per side
#define SBLK  256               // spread grid blocks
#define W4    (NK * ND / 4)     // 65600 float4 per weight matrix
#define MBLK  512               // main grid blocks (x 128 thr = 2048 warps)

// Per-block spread partials {dmax, dmin, emax, emin}; deterministic overwrite
// each launch -> no reset node, no atomics, graph-safe.
__device__ float4 g_part[SBLK];

__device__ __forceinline__ float wmax(float v) {
    #pragma unroll
    for (int o = 16; o > 0; o >>= 1) v = fmaxf(v, __shfl_xor_sync(0xffffffffu, v, o));
    return v;
}
__device__ __forceinline__ float wmin(float v) {
    #pragma unroll
    for (int o = 16; o > 0; o >>= 1) v = fminf(v, __shfl_xor_sync(0xffffffffu, v, o));
    return v;
}
__device__ __forceinline__ float4 max4(float4 a, float v, float4 w) {
    a.x = fmaxf(a.x, v + w.x); a.y = fmaxf(a.y, v + w.y);
    a.z = fmaxf(a.z, v + w.z); a.w = fmaxf(a.w, v + w.w);
    return a;
}
__device__ __forceinline__ float4 min4(float4 a, float v, float4 w) {
    a.x = fminf(a.x, v - w.x); a.y = fminf(a.y, v - w.y);
    a.z = fminf(a.z, v - w.z); a.w = fminf(a.w, v - w.w);
    return a;
}

// ---------------------------------------------------------------------------
// Kernel 1: per-block weight max/min partials (both matrices).
// ---------------------------------------------------------------------------
__global__ __launch_bounds__(256) void spread_kernel(
    const float4* __restrict__ dil4, const float4* __restrict__ ero4)
{
    const int tid = threadIdx.x;
    const int i   = blockIdx.x * 256 + tid;    // 0..65535

    float4 d = dil4[i], e = ero4[i];
    float dmx = fmaxf(fmaxf(d.x, d.y), fmaxf(d.z, d.w));
    float dmn = fminf(fminf(d.x, d.y), fminf(d.z, d.w));
    float emx = fmaxf(fmaxf(e.x, e.y), fmaxf(e.z, e.w));
    float emn = fminf(fminf(e.x, e.y), fminf(e.z, e.w));

    if (blockIdx.x == 0 && tid < W4 - 65536) {  // 64-float4 tails
        float4 d2 = dil4[65536 + tid], e2 = ero4[65536 + tid];
        dmx = fmaxf(dmx, fmaxf(fmaxf(d2.x, d2.y), fmaxf(d2.z, d2.w)));
        dmn = fminf(dmn, fminf(fminf(d2.x, d2.y), fminf(d2.z, d2.w)));
        emx = fmaxf(emx, fmaxf(fmaxf(e2.x, e2.y), fmaxf(e2.z, e2.w)));
        emn = fminf(emn, fminf(fminf(e2.x, e2.y), fminf(e2.z, e2.w)));
    }

    __shared__ float s[4][8];
    dmx = wmax(dmx); dmn = wmin(dmn); emx = wmax(emx); emn = wmin(emn);
    const int w = tid >> 5, l = tid & 31;
    if (l == 0) { s[0][w] = dmx; s[1][w] = dmn; s[2][w] = emx; s[3][w] = emn; }
    __syncthreads();
    if (w == 0) {
        dmx = (l < 8) ? s[0][l] : -CUDART_INF_F;  dmx = wmax(dmx);
        dmn = (l < 8) ? s[1][l] :  CUDART_INF_F;  dmn = wmin(dmn);
        emx = (l < 8) ? s[2][l] : -CUDART_INF_F;  emx = wmax(emx);
        emn = (l < 8) ? s[3][l] :  CUDART_INF_F;  emn = wmin(emn);
        if (l == 0) g_part[blockIdx.x] = make_float4(dmx, dmn, emx, emn);
    }
}

// ---------------------------------------------------------------------------
// Kernel 2: warp-autonomous main. One warp per (row, side); no smem, no
// __syncthreads. Launched with PDL: x-loads issue before griddepcontrol.wait,
// overlapping the spread kernel. Exact pruning:
//   dilation argmax k needs  x[k] >= xmax - (Dmax-Dmin)
//   erosion  argmin k needs  x[k] <= xmin + (Emax-Emin)
// Ballot-driven candidate loop handles ANY candidate count (worst case =
// exact brute force), so correctness never depends on pruning efficacy.
// ---------------------------------------------------------------------------
__global__ __launch_bounds__(128) void dilate_erode_main(
    const float4* __restrict__ x4,
    const float4* __restrict__ dil4,
    const float4* __restrict__ ero4,
    float4* __restrict__ out4)
{
    const int lane = threadIdx.x & 31;
    const int gw   = blockIdx.x * 4 + (threadIdx.x >> 5);  // 0..2047
    const int b    = gw >> 1;
    const int side = gw & 1;        // 0 = erosion, 1 = dilation

    // ---- x-row loads: issued before the PDL wait (overlap spread kernel) ----
    float4 f[8];
    #pragma unroll
    for (int q = 0; q < 8; q++)
        f[q] = x4[b * 256 + q * 32 + lane];   // feature k = q*128 + lane*4 + c

    // ---- wait for spread kernel results ----
    asm volatile("griddepcontrol.wait;" ::: "memory");

    float4 p[8];
    #pragma unroll
    for (int q = 0; q < 8; q++)
        p[q] = g_part[q * 32 + lane];

    if (side) {
        // =========================== DILATION ===========================
        float pmx = -CUDART_INF_F, pmn = CUDART_INF_F;
        #pragma unroll
        for (int q = 0; q < 8; q++) { pmx = fmaxf(pmx, p[q].x); pmn = fminf(pmn, p[q].y); }
        const float spreadD = wmax(pmx) - wmin(pmn);

        float gmx[8];
        float vmx = 0.0f;                       // bias feature value 0
        #pragma unroll
        for (int q = 0; q < 8; q++) {
            gmx[q] = fmaxf(fmaxf(f[q].x, f[q].y), fmaxf(f[q].z, f[q].w));
            vmx = fmaxf(vmx, gmx[q]);
        }
        const float thD = wmax(vmx) - spreadD;  // inclusive -> exact

        float4 a0, a1;
        a0.x = a0.y = a0.z = a0.w = -CUDART_INF_F;  a1 = a0;

        #pragma unroll
        for (int q = 0; q < 8; q++) {
            unsigned m = __ballot_sync(0xffffffffu, gmx[q] >= thD);
            while (m) {
                int L = __ffs(m) - 1;  m &= m - 1;
                float v0 = __shfl_sync(0xffffffffu, f[q].x, L);
                float v1 = __shfl_sync(0xffffffffu, f[q].y, L);
                float v2 = __shfl_sync(0xffffffffu, f[q].z, L);
                float v3 = __shfl_sync(0xffffffffu, f[q].w, L);
                int kb = q * 128 + L * 4;
                if (v0 >= thD) { a0 = max4(a0, v0, dil4[(kb  )*64 + 2*lane]); a1 = max4(a1, v0, dil4[(kb  )*64 + 2*lane+1]); }
                if (v1 >= thD) { a0 = max4(a0, v1, dil4[(kb+1)*64 + 2*lane]); a1 = max4(a1, v1, dil4[(kb+1)*64 + 2*lane+1]); }
                if (v2 >= thD) { a0 = max4(a0, v2, dil4[(kb+2)*64 + 2*lane]); a1 = max4(a1, v2, dil4[(kb+2)*64 + 2*lane+1]); }
                if (v3 >= thD) { a0 = max4(a0, v3, dil4[(kb+3)*64 + 2*lane]); a1 = max4(a1, v3, dil4[(kb+3)*64 + 2*lane+1]); }
            }
        }
        if (0.0f >= thD) {   // bias k = NF, value 0 (warp-uniform)
            a0 = max4(a0, 0.0f, dil4[NF*64 + 2*lane]);
            a1 = max4(a1, 0.0f, dil4[NF*64 + 2*lane+1]);
        }
        out4[b * 128 + 64 + 2*lane    ] = a0;   // dilated cols [256,512)
        out4[b * 128 + 64 + 2*lane + 1] = a1;
    } else {
        // =========================== EROSION ============================
        float pmx = -CUDART_INF_F, pmn = CUDART_INF_F;
        #pragma unroll
        for (int q = 0; q < 8; q++) { pmx = fmaxf(pmx, p[q].z); pmn = fminf(pmn, p[q].w); }
        const float spreadE = wmax(pmx) - wmin(pmn);

        float gmn[8];
        float vmn = 0.0f;                       // bias feature value 0
        #pragma unroll
        for (int q = 0; q < 8; q++) {
            gmn[q] = fminf(fminf(f[q].x, f[q].y), fminf(f[q].z, f[q].w));
            vmn = fminf(vmn, gmn[q]);
        }
        const float thE = wmin(vmn) + spreadE;  // inclusive -> exact

        float4 a0, a1;
        a0.x = a0.y = a0.z = a0.w = CUDART_INF_F;  a1 = a0;

        #pragma unroll
        for (int q = 0; q < 8; q++) {
            unsigned m = __ballot_sync(0xffffffffu, gmn[q] <= thE);
            while (m) {
                int L = __ffs(m) - 1;  m &= m - 1;
                float v0 = __shfl_sync(0xffffffffu, f[q].x, L);
                float v1 = __shfl_sync(0xffffffffu, f[q].y, L);
                float v2 = __shfl_sync(0xffffffffu, f[q].z, L);
                float v3 = __shfl_sync(0xffffffffu, f[q].w, L);
                int kb = q * 128 + L * 4;
                if (v0 <= thE) { a0 = min4(a0, v0, ero4[(kb  )*64 + 2*lane]); a1 = min4(a1, v0, ero4[(kb  )*64 + 2*lane+1]); }
                if (v1 <= thE) { a0 = min4(a0, v1, ero4[(kb+1)*64 + 2*lane]); a1 = min4(a1, v1, ero4[(kb+1)*64 + 2*lane+1]); }
                if (v2 <= thE) { a0 = min4(a0, v2, ero4[(kb+2)*64 + 2*lane]); a1 = min4(a1, v2, ero4[(kb+2)*64 + 2*lane+1]); }
                if (v3 <= thE) { a0 = min4(a0, v3, ero4[(kb+3)*64 + 2*lane]); a1 = min4(a1, v3, ero4[(kb+3)*64 + 2*lane+1]); }
            }
        }
        if (0.0f <= thE) {   // bias k = NF, value 0 (warp-uniform)
            a0 = min4(a0, 0.0f, ero4[NF*64 + 2*lane]);
            a1 = min4(a1, 0.0f, ero4[NF*64 + 2*lane+1]);
        }
        out4[b * 128 + 2*lane    ] = a0;        // eroded cols [0,256)
        out4[b * 128 + 2*lane + 1] = a1;
    }
}

extern "C" void kernel_launch(void* const* d_in, const int* in_sizes, int n_in,
                              void* d_out, int out_size)
{
    (void)in_sizes; (void)n_in; (void)out_size;
    const float4* x4   = (const float4*)d_in[0];
    const float4* dil4 = (const float4*)d_in[1];
    const float4* ero4 = (const float4*)d_in[2];
    float4* out4 = (float4*)d_out;

    spread_kernel<<<SBLK, 256>>>(dil4, ero4);

    // PDL: main launches while spread runs; main's prologue (x-loads) overlaps
    // spread execution; griddepcontrol.wait gates the g_part reads.
    cudaLaunchConfig_t cfg = {};
    cfg.gridDim  = dim3(MBLK, 1, 1);
    cfg.blockDim = dim3(128, 1, 1);
    cfg.dynamicSmemBytes = 0;
    cfg.stream = 0;
    cudaLaunchAttribute attr[1];
    attr[0].id = cudaLaunchAttributeProgrammaticStreamSerialization;
    attr[0].val.programmaticStreamSerializationAllowed = 1;
    cfg.attrs = attr;
    cfg.numAttrs = 1;
    cudaLaunchKernelEx(&cfg, dilate_erode_main, x4, dil4, ero4, out4);
}

// round 7
// speedup vs baseline: 1.0251x; 1.0251x over previous
#include <cuda_runtime.h>
#include <math_constants.h>

#define NF    1024
#define NK    (NF + 1)
#define ND    256               // output units per side
#define NOUT  512
#define NBLK  1024
#define NTHR  256
#define W4    (NK * ND / 4)     // 65600 float4 per weight matrix
#define WB    256               // blocks that reduce weights (1 float4/thread)
#define CAP   128               // candidate capacity (overflow -> exact fallback)

// Persistent device state. g_part is deterministically overwritten each launch.
// g_count/g_sense form a reset-free sense-reversing grid barrier (count returns
// to 0 at每 release; sense increases monotonically across launches).
__device__ float4   g_part[WB];
__device__ int      g_count = 0;
__device__ unsigned g_sense = 0;

__device__ __forceinline__ float wmax(float v) {
    #pragma unroll
    for (int o = 16; o > 0; o >>= 1) v = fmaxf(v, __shfl_xor_sync(0xffffffffu, v, o));
    return v;
}
__device__ __forceinline__ float wmin(float v) {
    #pragma unroll
    for (int o = 16; o > 0; o >>= 1) v = fminf(v, __shfl_xor_sync(0xffffffffu, v, o));
    return v;
}

__global__ __launch_bounds__(NTHR, 8) void dilate_erode_fused(
    const float* __restrict__ x,
    const float* __restrict__ dil,
    const float* __restrict__ ero,
    float* __restrict__ out)
{
    __shared__ float sA[6][8];      // warp partials: xmx,xmn,dmx,dmn,emx,emn
    __shared__ float s_fin[6];      // finalized block values
    __shared__ float s_sp[4][8];    // post-barrier spread warp partials
    __shared__ float s_spread[2];
    __shared__ int   nD, nE;
    __shared__ int   kD[CAP], kE[CAP];
    __shared__ float vD[CAP], vE[CAP];

    const int tid = threadIdx.x;
    const int b   = blockIdx.x;
    const int w   = tid >> 5, l = tid & 31;

    if (tid == 0) { nD = 0; nE = 0; }

    // ---- issue x-row load first (overlaps the weight streaming below) ----
    const float4 f = ((const float4*)x)[b * 256 + tid];   // features tid*4..+3

    // ---- PHASE A: weight chunk reduce (blocks 0..WB-1 only) ----
    float dmx = -CUDART_INF_F, dmn = CUDART_INF_F;
    float emx = -CUDART_INF_F, emn = CUDART_INF_F;
    if (b < WB) {
        const float4 d = ((const float4*)dil)[b * 256 + tid];
        const float4 e = ((const float4*)ero)[b * 256 + tid];
        dmx = fmaxf(fmaxf(d.x, d.y), fmaxf(d.z, d.w));
        dmn = fminf(fminf(d.x, d.y), fminf(d.z, d.w));
        emx = fmaxf(fmaxf(e.x, e.y), fmaxf(e.z, e.w));
        emn = fminf(fminf(e.x, e.y), fminf(e.z, e.w));
        if (b == 0 && tid < W4 - WB * 256) {          // 64-float4 tails
            const float4 d2 = ((const float4*)dil)[WB * 256 + tid];
            const float4 e2 = ((const float4*)ero)[WB * 256 + tid];
            dmx = fmaxf(dmx, fmaxf(fmaxf(d2.x, d2.y), fmaxf(d2.z, d2.w)));
            dmn = fminf(dmn, fminf(fminf(d2.x, d2.y), fminf(d2.z, d2.w)));
            emx = fmaxf(emx, fmaxf(fmaxf(e2.x, e2.y), fmaxf(e2.z, e2.w)));
            emn = fminf(emn, fminf(fminf(e2.x, e2.y), fminf(e2.z, e2.w)));
        }
    }

    // ---- row extrema (bias value 0 folded into init) ----
    float xmx = fmaxf(0.0f, fmaxf(fmaxf(f.x, f.y), fmaxf(f.z, f.w)));
    float xmn = fminf(0.0f, fminf(fminf(f.x, f.y), fminf(f.z, f.w)));

    xmx = wmax(xmx); xmn = wmin(xmn);
    dmx = wmax(dmx); dmn = wmin(dmn);
    emx = wmax(emx); emn = wmin(emn);
    if (l == 0) {
        sA[0][w] = xmx; sA[1][w] = xmn; sA[2][w] = dmx;
        sA[3][w] = dmn; sA[4][w] = emx; sA[5][w] = emn;
    }
    __syncthreads();

    // warps 0..5 each finalize one quantity
    if (w < 6) {
        const bool is_min = (w == 1) || (w == 3) || (w == 5);
        float v = (l < 8) ? sA[w][l] : (is_min ? CUDART_INF_F : -CUDART_INF_F);
        v = is_min ? wmin(v) : wmax(v);
        if (l == 0) s_fin[w] = v;
    }
    __syncthreads();

    // ---- publish weight partial + grid barrier (reset-free, sense-reversing) ----
    if (tid == 0) {
        if (b < WB)
            g_part[b] = make_float4(s_fin[2], s_fin[3], s_fin[4], s_fin[5]);
        __threadfence();
        const unsigned s = *(volatile unsigned*)&g_sense;  // pre-arrival read
        const int old = atomicAdd(&g_count, 1);
        if (old == NBLK - 1) {
            g_count = 0;
            __threadfence();
            atomicExch(&g_sense, s + 1);                   // release
        } else {
            while (*(volatile unsigned*)&g_sense == s) __nanosleep(40);
        }
        __threadfence();
    }
    __syncthreads();

    // ---- global weight spread: reduce the 256 partials (L2-hot) ----
    {
        const float4 p = __ldcg(&g_part[tid]);             // one per thread
        float a = wmax(p.x), bn = wmin(p.y), c = wmax(p.z), dn = wmin(p.w);
        if (l == 0) { s_sp[0][w] = a; s_sp[1][w] = bn; s_sp[2][w] = c; s_sp[3][w] = dn; }
    }
    __syncthreads();
    if (w == 0) {
        float a  = (l < 8) ? s_sp[0][l] : -CUDART_INF_F;  a  = wmax(a);
        float bn = (l < 8) ? s_sp[1][l] :  CUDART_INF_F;  bn = wmin(bn);
        float c  = (l < 8) ? s_sp[2][l] : -CUDART_INF_F;  c  = wmax(c);
        float dn = (l < 8) ? s_sp[3][l] :  CUDART_INF_F;  dn = wmin(dn);
        if (l == 0) { s_spread[0] = a - bn; s_spread[1] = c - dn; }
    }
    __syncthreads();

    // Exact inclusive pruning bound:
    //   dilation argmax k needs  x[k] >= xmax - (Dmax-Dmin)
    //   erosion  argmin k needs  x[k] <= xmin + (Emax-Emin)
    const float thD = s_fin[0] - s_spread[0];
    const float thE = s_fin[1] + s_spread[1];

    // ---- candidate scan ----
    {
        const float vv[4] = { f.x, f.y, f.z, f.w };
        #pragma unroll
        for (int q = 0; q < 4; q++) {
            const int k = tid * 4 + q;
            if (vv[q] >= thD) { int p = atomicAdd(&nD, 1); if (p < CAP) { kD[p] = k; vD[p] = vv[q]; } }
            if (vv[q] <= thE) { int p = atomicAdd(&nE, 1); if (p < CAP) { kE[p] = k; vE[p] = vv[q]; } }
        }
        if (tid == 0) {     // bias feature k = NF, value 0
            if (0.0f >= thD) { int p = atomicAdd(&nD, 1); if (p < CAP) { kD[p] = NF; vD[p] = 0.0f; } }
            if (0.0f <= thE) { int p = atomicAdd(&nE, 1); if (p < CAP) { kE[p] = NF; vE[p] = 0.0f; } }
        }
    }
    __syncthreads();

    const int cD = nD, cE = nE;

    // ---- gather & accumulate: thread owns output column j = tid ----
    float dv = -CUDART_INF_F;
    if (cD <= CAP) {
        for (int c = 0; c < cD; c++)
            dv = fmaxf(dv, vD[c] + dil[kD[c] * ND + tid]);
    } else {                 // exact fallback (never expected)
        for (int k = 0; k < NK; k++) {
            const float xv = (k < NF) ? x[(size_t)b * NF + k] : 0.0f;
            dv = fmaxf(dv, xv + dil[k * ND + tid]);
        }
    }

    float ev = CUDART_INF_F;
    if (cE <= CAP) {
        for (int c = 0; c < cE; c++)
            ev = fminf(ev, vE[c] - ero[kE[c] * ND + tid]);
    } else {
        for (int k = 0; k < NK; k++) {
            const float xv = (k < NF) ? x[(size_t)b * NF + k] : 0.0f;
            ev = fminf(ev, xv - ero[k * ND + tid]);
        }
    }

    out[(size_t)b * NOUT + tid]      = ev;   // eroded  cols [0,256)
    out[(size_t)b * NOUT + ND + tid] = dv;   // dilated cols [256,512)
}

extern "C" void kernel_launch(void* const* d_in, const int* in_sizes, int n_in,
                              void* d_out, int out_size)
{
    (void)in_sizes; (void)n_in; (void)out_size;
    const float* x   = (const float*)d_in[0];
    const float* dil = (const float*)d_in[1];
    const float* ero = (const float*)d_in[2];
    float* out = (float*)d_out;

    dilate_erode_fused<<<NBLK, NTHR>>>(x, dil, ero, out);
}

// round 8
// speedup vs baseline: 1.2209x; 1.1910x over previous
#include <cuda_runtime.h>
#include <math_constants.h>

#define NF    1024
#define NK    (NF + 1)
#define ND    256               // output units per side
#define NOUT  512
#define W4    (NK * ND / 4)     // 65600 float4 per weight matrix
#define SBLK  512               // spread blocks: 0..255 dil, 256..511 ero
#define MBLK  1024
#define CAP   128               // candidate capacity (overflow -> exact fallback)

// Per-block spread partials {dmx, dmn, emx, emn}; deterministic overwrite each
// launch (dil blocks leave e-side at +-inf identity and vice versa).
__device__ float4 g_part[SBLK];

__device__ __forceinline__ float wmax(float v) {
    #pragma unroll
    for (int o = 16; o > 0; o >>= 1) v = fmaxf(v, __shfl_xor_sync(0xffffffffu, v, o));
    return v;
}
__device__ __forceinline__ float wmin(float v) {
    #pragma unroll
    for (int o = 16; o > 0; o >>= 1) v = fminf(v, __shfl_xor_sync(0xffffffffu, v, o));
    return v;
}

// ---------------------------------------------------------------------------
// Kernel 1: weight spread partials. 512 blocks x 256 thr, 1 float4/thread.
// Signals PDL dependents immediately so main can launch & run its prologue.
// ---------------------------------------------------------------------------
__global__ __launch_bounds__(256) void spread_kernel(
    const float4* __restrict__ dil4, const float4* __restrict__ ero4)
{
    asm volatile("griddepcontrol.launch_dependents;" ::: "memory");

    const int tid = threadIdx.x;
    const int blk = blockIdx.x;
    const bool is_d = (blk < 256);
    const float4* __restrict__ src = is_d ? dil4 : ero4;
    const int base = (is_d ? blk : blk - 256) * 256 + tid;   // 0..65535

    float4 v = src[base];
    float mx = fmaxf(fmaxf(v.x, v.y), fmaxf(v.z, v.w));
    float mn = fminf(fminf(v.x, v.y), fminf(v.z, v.w));
    if (base < W4 - 65536) {                                  // 64-float4 tail
        float4 t = src[base + 65536];
        mx = fmaxf(mx, fmaxf(fmaxf(t.x, t.y), fmaxf(t.z, t.w)));
        mn = fminf(mn, fminf(fminf(t.x, t.y), fminf(t.z, t.w)));
    }

    __shared__ float s[2][8];
    mx = wmax(mx); mn = wmin(mn);
    const int w = tid >> 5, l = tid & 31;
    if (l == 0) { s[0][w] = mx; s[1][w] = mn; }
    __syncthreads();
    if (w == 0) {
        mx = (l < 8) ? s[0][l] : -CUDART_INF_F;  mx = wmax(mx);
        mn = (l < 8) ? s[1][l] :  CUDART_INF_F;  mn = wmin(mn);
        if (l == 0)
            g_part[blk] = is_d
                ? make_float4(mx, mn, -CUDART_INF_F,  CUDART_INF_F)
                : make_float4(-CUDART_INF_F, CUDART_INF_F, mx, mn);
    }
}

// ---------------------------------------------------------------------------
// Kernel 2: block b = batch row b. PDL: x-load + row-reduce BEFORE the wait.
// Exact inclusive pruning:
//   dilation argmax k needs  x[k] >= xmax - (Dmax-Dmin)
//   erosion  argmin k needs  x[k] <= xmin + (Emax-Emin)
// ---------------------------------------------------------------------------
__global__ __launch_bounds__(256) void dilate_erode_main(
    const float* __restrict__ x,
    const float* __restrict__ dil,
    const float* __restrict__ ero,
    float* __restrict__ out)
{
    __shared__ float s[6][8];     // warp partials: xmx,xmn | dmx,dmn,emx,emn
    __shared__ int   nD, nE;
    __shared__ int   kD[CAP], kE[CAP];
    __shared__ float vD[CAP], vE[CAP];

    const int tid = threadIdx.x;
    const int b   = blockIdx.x;
    const int w   = tid >> 5, l = tid & 31;

    if (tid == 0) { nD = 0; nE = 0; }

    // ---- PROLOGUE (overlaps spread kernel): x row load + row extrema ----
    const float4 f = ((const float4*)x)[b * 256 + tid];   // features tid*4..+3
    float xmx = fmaxf(0.0f, fmaxf(fmaxf(f.x, f.y), fmaxf(f.z, f.w)));  // bias 0
    float xmn = fminf(0.0f, fminf(fminf(f.x, f.y), fminf(f.z, f.w)));
    xmx = wmax(xmx); xmn = wmin(xmn);
    if (l == 0) { s[0][w] = xmx; s[1][w] = xmn; }

    // ---- wait for spread results, reduce the 512 partials (L2-hot) ----
    asm volatile("griddepcontrol.wait;" ::: "memory");
    {
        const float4 p0 = g_part[tid];
        const float4 p1 = g_part[tid + 256];
        float dmx = fmaxf(p0.x, p1.x), dmn = fminf(p0.y, p1.y);
        float emx = fmaxf(p0.z, p1.z), emn = fminf(p0.w, p1.w);
        dmx = wmax(dmx); dmn = wmin(dmn); emx = wmax(emx); emn = wmin(emn);
        if (l == 0) { s[2][w] = dmx; s[3][w] = dmn; s[4][w] = emx; s[5][w] = emn; }
    }
    __syncthreads();   // sync #1: all warp partials visible

    // ---- every warp finalizes all 6 quantities (no second sync needed) ----
    float thD, thE;
    {
        float a0 = (l < 8) ? s[0][l] : -CUDART_INF_F;   // xmax
        float a1 = (l < 8) ? s[1][l] :  CUDART_INF_F;   // xmin
        float a2 = (l < 8) ? s[2][l] : -CUDART_INF_F;   // dmax
        float a3 = (l < 8) ? s[3][l] :  CUDART_INF_F;   // dmin
        float a4 = (l < 8) ? s[4][l] : -CUDART_INF_F;   // emax
        float a5 = (l < 8) ? s[5][l] :  CUDART_INF_F;   // emin
        a0 = wmax(a0); a1 = wmin(a1); a2 = wmax(a2);
        a3 = wmin(a3); a4 = wmax(a4); a5 = wmin(a5);
        thD = a0 - (a2 - a3);   // inclusive -> exact
        thE = a1 + (a4 - a5);
    }

    // ---- candidate scan ----
    {
        const float vv[4] = { f.x, f.y, f.z, f.w };
        #pragma unroll
        for (int q = 0; q < 4; q++) {
            const int k = tid * 4 + q;
            if (vv[q] >= thD) { int p = atomicAdd(&nD, 1); if (p < CAP) { kD[p] = k; vD[p] = vv[q]; } }
            if (vv[q] <= thE) { int p = atomicAdd(&nE, 1); if (p < CAP) { kE[p] = k; vE[p] = vv[q]; } }
        }
        if (tid == 0) {     // bias feature k = NF, value 0
            if (0.0f >= thD) { int p = atomicAdd(&nD, 1); if (p < CAP) { kD[p] = NF; vD[p] = 0.0f; } }
            if (0.0f <= thE) { int p = atomicAdd(&nE, 1); if (p < CAP) { kE[p] = NF; vE[p] = 0.0f; } }
        }
    }
    __syncthreads();   // sync #2: candidate lists complete

    const int cD = nD, cE = nE;

    // ---- interleaved gather: 2 independent LDGs per iteration ----
    float dv = -CUDART_INF_F;
    float ev =  CUDART_INF_F;
    if (cD <= CAP && cE <= CAP) {
        const int cM = (cD > cE) ? cD : cE;
        for (int c = 0; c < cM; c++) {
            float wd = 0.0f, we = 0.0f;
            const bool hd = (c < cD), he = (c < cE);
            if (hd) wd = dil[kD[c] * ND + tid];   // both loads issue before use
            if (he) we = ero[kE[c] * ND + tid];
            if (hd) dv = fmaxf(dv, vD[c] + wd);
            if (he) ev = fminf(ev, vE[c] - we);
        }
    } else {            // exact fallback (never expected)
        for (int k = 0; k < NK; k++) {
            const float xv = (k < NF) ? x[(size_t)b * NF + k] : 0.0f;
            dv = fmaxf(dv, xv + dil[k * ND + tid]);
            ev = fminf(ev, xv - ero[k * ND + tid]);
        }
    }

    out[(size_t)b * NOUT + tid]      = ev;   // eroded  cols [0,256)
    out[(size_t)b * NOUT + ND + tid] = dv;   // dilated cols [256,512)
}

extern "C" void kernel_launch(void* const* d_in, const int* in_sizes, int n_in,
                              void* d_out, int out_size)
{
    (void)in_sizes; (void)n_in; (void)out_size;
    const float* x   = (const float*)d_in[0];
    const float* dil = (const float*)d_in[1];
    const float* ero = (const float*)d_in[2];
    float* out = (float*)d_out;

    spread_kernel<<<SBLK, 256>>>((const float4*)dil, (const float4*)ero);

    // PDL: main launches while spread runs; prologue (x-load + row reduce)
    // overlaps spread execution; griddepcontrol.wait gates the g_part reads.
    cudaLaunchConfig_t cfg = {};
    cfg.gridDim  = dim3(MBLK, 1, 1);
    cfg.blockDim = dim3(256, 1, 1);
    cfg.dynamicSmemBytes = 0;
    cfg.stream = 0;
    cudaLaunchAttribute attr[1];
    attr[0].id = cudaLaunchAttributeProgrammaticStreamSerialization;
    attr[0].val.programmaticStreamSerializationAllowed = 1;
    cfg.attrs = attr;
    cfg.numAttrs = 1;
    cudaLaunchKernelEx(&cfg, dilate_erode_main, x, dil, ero, out);
}